// round 7
// baseline (speedup 1.0000x reference)
#include <cuda_runtime.h>
#include <cstdint>

#define NN 3072
#define DD 128
#define HID 256
#define NAA 20
#define NH 8
#define TM 16          // rows per prep block
#define JT 64          // j-tile per pair CTA
#define IT 16          // i-rows per pair CTA
#define CSTRIDE 164    // padded ctilde row stride (floats): banks 4*ri, 16B aligned

typedef unsigned long long ull;

// Scratch (allocation-free rule: __device__ globals)
// dgate, block-transposed: float index = jb*10240 + (xp*4 + b/2)*256 + jj*4 + (b&1)*2 + (x&1)
__device__ __align__(16) float g_dgT[48 * 40 * 256];
// ctilde: row layout [xp*16 + b*2 + e], padded to 164 floats per row
__device__ __align__(16) float g_ctilde[NN * CSTRIDE];

__device__ __forceinline__ float gelu_tanh(float v) {
    float u = 0.7978845608028654f * (v + 0.044715f * v * v * v);
    return 0.5f * v * (1.0f + tanhf(u));
}

__device__ __forceinline__ ull fma2(ull a, ull b, ull c) {
    ull d;
    asm("fma.rn.f32x2 %0, %1, %2, %3;" : "=l"(d) : "l"(a), "l"(b), "l"(c));
    return d;
}

__device__ __forceinline__ uint32_t smem_u32(const void* p) {
    uint32_t a;
    asm("{ .reg .u64 t; cvta.to.shared.u64 t, %1; cvt.u32.u64 %0, t; }" : "=r"(a) : "l"(p));
    return a;
}

// ============================================================================
// Kernel A: fused MLP + projections + ctilde / dgate precompute (TM=16, 256T)
// ============================================================================
__global__ __launch_bounds__(256) void prep_kernel(
    const float* __restrict__ local, const int* __restrict__ aa,
    const float* __restrict__ W1, const float* __restrict__ W2,
    const float* __restrict__ Wc, const float* __restrict__ Wg,
    const float* __restrict__ iw)
{
    __shared__ __align__(16) float xs[TM][DD];
    __shared__ __align__(16) float Hs[TM][HID];
    __shared__ __align__(16) float Fs[TM][DD];
    __shared__ __align__(16) float dcs[TM][160];
    __shared__ __align__(16) float dgs[40 * 64];
    __shared__ float iws[NH * NH * NAA];
    __shared__ int aas[TM];

    const int tid = threadIdx.x;
    const int r0 = blockIdx.x * TM;

    for (int t = tid; t < TM * DD; t += 256) {
        int r = t / DD, k = t % DD;
        xs[r][k] = local[(size_t)(r0 + r) * DD + k];
    }
    for (int t = tid; t < NH * NH * NAA; t += 256) iws[t] = iw[t];
    if (tid < TM) aas[tid] = aa[r0 + tid];
    __syncthreads();

    // ---- stage 1 ----
    {
        float acc[TM];
#pragma unroll
        for (int r = 0; r < TM; r++) acc[r] = 0.f;
        const int col = tid;
#pragma unroll 8
        for (int k = 0; k < DD; k += 4) {
            float w0 = W1[(size_t)(k + 0) * HID + col];
            float w1 = W1[(size_t)(k + 1) * HID + col];
            float w2 = W1[(size_t)(k + 2) * HID + col];
            float w3 = W1[(size_t)(k + 3) * HID + col];
#pragma unroll
            for (int r = 0; r < TM; r++) {
                float4 xv = *(const float4*)&xs[r][k];
                acc[r] = fmaf(xv.x, w0, fmaf(xv.y, w1, fmaf(xv.z, w2, fmaf(xv.w, w3, acc[r]))));
            }
        }
#pragma unroll
        for (int r = 0; r < TM; r++) {
            acc[r] += W1[(size_t)(DD + aas[r]) * HID + col];
            Hs[r][col] = gelu_tanh(acc[r]);
        }
    }
    __syncthreads();

    // ---- stage 2 ----
    {
        float acc[8];
#pragma unroll
        for (int r = 0; r < 8; r++) acc[r] = 0.f;
        const int col = tid & 127;
        const int rb = (tid >> 7) * 8;
#pragma unroll 8
        for (int k = 0; k < HID; k += 4) {
            float w0 = W2[(size_t)(k + 0) * DD + col];
            float w1 = W2[(size_t)(k + 1) * DD + col];
            float w2 = W2[(size_t)(k + 2) * DD + col];
            float w3 = W2[(size_t)(k + 3) * DD + col];
#pragma unroll
            for (int r = 0; r < 8; r++) {
                float4 hv = *(const float4*)&Hs[rb + r][k];
                acc[r] = fmaf(hv.x, w0, fmaf(hv.y, w1, fmaf(hv.z, w2, fmaf(hv.w, w3, acc[r]))));
            }
        }
#pragma unroll
        for (int r = 0; r < 8; r++) Fs[rb + r][col] = acc[r];
    }
    __syncthreads();

    // ---- stage 3 ----
    for (int c = tid; c < 320; c += 256) {
        float acc[TM];
#pragma unroll
        for (int r = 0; r < TM; r++) acc[r] = 0.f;
        const float* W = (c < 160) ? (Wc + c) : (Wg + (c - 160));
#pragma unroll 8
        for (int k = 0; k < DD; k += 4) {
            float w0 = W[(size_t)(k + 0) * 160];
            float w1 = W[(size_t)(k + 1) * 160];
            float w2 = W[(size_t)(k + 2) * 160];
            float w3 = W[(size_t)(k + 3) * 160];
#pragma unroll
            for (int r = 0; r < TM; r++) {
                float4 fv = *(const float4*)&Fs[r][k];
                acc[r] = fmaf(fv.x, w0, fmaf(fv.y, w1, fmaf(fv.z, w2, fmaf(fv.w, w3, acc[r]))));
            }
        }
        if (c < 160) {
#pragma unroll
            for (int r = 0; r < TM; r++) dcs[r][c] = acc[r];
        } else {
            int cc = c - 160;
            int b = cc / NAA, x = cc % NAA;
            int row = (x >> 1) * 4 + (b >> 1);
            int e   = (b & 1) * 2 + (x & 1);
#pragma unroll
            for (int r = 0; r < TM; r++)
                dgs[row * 64 + r * 4 + e] = gelu_tanh(acc[r]);
        }
    }
    __syncthreads();

    // ---- coalesced copy: dgs -> g_dgT ----
    {
        const int jb = r0 >> 6;
        const int jo = (r0 & 63) >> 2;
        const float4* src = (const float4*)dgs;
        float4* dst = (float4*)g_dgT;
        for (int t = tid; t < 640; t += 256) {
            int row = t >> 4, q = t & 15;
            dst[(size_t)jb * 2560 + row * 64 + jo * 4 + q] = src[row * 16 + q];
        }
    }

    // ---- stage 4: ctilde (padded row stride) ----
    for (int t = tid; t < TM * 160; t += 256) {
        int r = t / 160, rem = t % 160;
        int b = rem / NAA, x = rem % NAA;
        float s = 0.f;
#pragma unroll
        for (int a = 0; a < NH; a++)
            s = fmaf(dcs[r][a * NAA + x], iws[a * 160 + b * NAA + x], s);
        g_ctilde[(size_t)(r0 + r) * CSTRIDE + (x >> 1) * 16 + b * 2 + (x & 1)] = s;
    }
}

// ============================================================================
// Kernel B: pairwise bilinear + log_softmax — 2D lane map (8i x 4j per warp)
// Both operand streams conflict-free at ~1 wf per LDS.128.
// smem: gs2 40960 | cs 10496 | stage 8*5248=41984 | mbar
// ============================================================================
#define SM_GS   0
#define SM_CS   40960
#define SM_STG  51456
#define SM_MBAR 93440
#define SM_TOT  93456

__global__ __launch_bounds__(256, 2) void pair_kernel(float* __restrict__ out)
{
    extern __shared__ __align__(16) char sm[];
    const ulonglong2* gs2 = (const ulonglong2*)(sm + SM_GS);  // [40][64]
    const float*      cs  = (const float*)(sm + SM_CS);       // [16][CSTRIDE]

    const uint32_t sb   = smem_u32(sm);
    const uint32_t mbar = sb + SM_MBAR;

    const int tid  = threadIdx.x;
    const int lane = tid & 31;
    const int wid  = tid >> 5;
    const int ri   = lane >> 2;      // 0..7 (i within half-tile)
    const int cj   = lane & 3;       // 0..3 (j pair-group within octet)
    const int i0   = blockIdx.x * IT;
    const int jb   = blockIdx.y;

    if (tid == 0) {
        asm volatile("mbarrier.init.shared::cta.b64 [%0], %1;" :: "r"(mbar), "r"(1) : "memory");
    }
    __syncthreads();
    if (tid == 0) {
        asm volatile("mbarrier.arrive.expect_tx.shared::cta.b64 _, [%0], %1;"
                     :: "r"(mbar), "r"(51456) : "memory");
        asm volatile("cp.async.bulk.shared::cta.global.mbarrier::complete_tx::bytes [%0], [%1], %2, [%3];"
                     :: "r"(sb + SM_GS), "l"(g_dgT + (size_t)jb * 10240), "r"(40960), "r"(mbar) : "memory");
        asm volatile("cp.async.bulk.shared::cta.global.mbarrier::complete_tx::bytes [%0], [%1], %2, [%3];"
                     :: "r"(sb + SM_CS), "l"(g_ctilde + (size_t)i0 * CSTRIDE), "r"(10496), "r"(mbar) : "memory");
    }
    asm volatile("{\n\t.reg .pred P;\n"
                 "W%=: mbarrier.try_wait.parity.shared::cta.b64 P, [%0], 0;\n\t"
                 "@!P bra W%=;\n\t}" :: "r"(mbar) : "memory");
    __syncthreads();

    // thread's operand bases
    const ulonglong2* gbase = gs2 + wid * 8 + cj * 2;     // + tj + row*64
    const float*      cbase = cs + ri * CSTRIDE;          // + r*8*CSTRIDE + ...

    ull acc[2][2][10];                                    // [r][tj][xp] = 80 regs
#pragma unroll
    for (int r = 0; r < 2; r++)
#pragma unroll
        for (int t = 0; t < 2; t++)
#pragma unroll
            for (int q = 0; q < 10; q++) acc[r][t][q] = 0ULL;

#pragma unroll
    for (int xp = 0; xp < 10; xp++) {
#pragma unroll
        for (int bq = 0; bq < 4; bq++) {
            ulonglong2 gA = gbase[(xp * 4 + bq) * 64];        // tj = 0
            ulonglong2 gB = gbase[(xp * 4 + bq) * 64 + 1];    // tj = 1
            longlong2 c0 = *(const longlong2*)(cbase + xp * 16 + bq * 4);
            longlong2 c1 = *(const longlong2*)(cbase + 8 * CSTRIDE + xp * 16 + bq * 4);
            acc[0][0][xp] = fma2((ull)c0.y, gA.y, fma2((ull)c0.x, gA.x, acc[0][0][xp]));
            acc[0][1][xp] = fma2((ull)c0.y, gB.y, fma2((ull)c0.x, gB.x, acc[0][1][xp]));
            acc[1][0][xp] = fma2((ull)c1.y, gA.y, fma2((ull)c1.x, gA.x, acc[1][0][xp]));
            acc[1][1][xp] = fma2((ull)c1.y, gB.y, fma2((ull)c1.x, gB.x, acc[1][1][xp]));
        }
    }

    // ---- epilogue: softmax, stage [8i][8j][20] (i-stride CSTRIDE), bulk out ----
    float* wstage = (float*)(sm + SM_STG) + wid * 1312;       // 8*164 floats
    const uint32_t wstage_u32 = sb + SM_STG + wid * 5248;
    const int jcol0 = jb * JT + wid * 8;

#pragma unroll
    for (int r = 0; r < 2; r++) {
        if (r == 1) {
            if (lane == 0)
                asm volatile("cp.async.bulk.wait_group.read 0;" ::: "memory");
            __syncwarp();
        }
#pragma unroll
        for (int tj = 0; tj < 2; tj++) {
            float l[20];
#pragma unroll
            for (int q = 0; q < 10; q++) {
                l[2 * q]     = __uint_as_float((unsigned)(acc[r][tj][q] & 0xffffffffu));
                l[2 * q + 1] = __uint_as_float((unsigned)(acc[r][tj][q] >> 32));
            }
            float m = l[0];
#pragma unroll
            for (int x = 1; x < 20; x++) m = fmaxf(m, l[x]);
            float s = 0.f;
#pragma unroll
            for (int x = 0; x < 20; x++) s += __expf(l[x] - m);
            float lse = m + __logf(s);

            float* tp = wstage + ri * CSTRIDE + (cj * 2 + tj) * 20;
#pragma unroll
            for (int q = 0; q < 5; q++) {
                float4 o = make_float4(l[4 * q] - lse, l[4 * q + 1] - lse,
                                       l[4 * q + 2] - lse, l[4 * q + 3] - lse);
                *(float4*)(tp + 4 * q) = o;
            }
        }
        __syncwarp();

        if (lane == 0) {
            asm volatile("fence.proxy.async.shared::cta;" ::: "memory");
#pragma unroll
            for (int ii = 0; ii < 8; ii++) {
                float* gdst = out + ((size_t)(i0 + r * 8 + ii) * NN + jcol0) * NAA;
                asm volatile("cp.async.bulk.global.shared::cta.bulk_group [%0], [%1], %2;"
                             :: "l"(gdst), "r"(wstage_u32 + ii * 656), "r"(640) : "memory");
            }
            asm volatile("cp.async.bulk.commit_group;" ::: "memory");
        }
    }
    if (lane == 0)
        asm volatile("cp.async.bulk.wait_group 0;" ::: "memory");
}

// ============================================================================
extern "C" void kernel_launch(void* const* d_in, const int* in_sizes, int n_in,
                              void* d_out, int out_size)
{
    const float* local = (const float*)d_in[0];
    const int*   aa    = (const int*)d_in[1];
    const float* W1    = (const float*)d_in[2];
    const float* W2    = (const float*)d_in[3];
    const float* Wc    = (const float*)d_in[4];
    const float* Wg    = (const float*)d_in[5];
    const float* iw    = (const float*)d_in[6];
    float* out = (float*)d_out;

    prep_kernel<<<NN / TM, 256>>>(local, aa, W1, W2, Wc, Wg, iw);

    cudaFuncSetAttribute(pair_kernel, cudaFuncAttributeMaxDynamicSharedMemorySize, SM_TOT);
    dim3 grid(NN / IT, NN / JT);
    pair_kernel<<<grid, 256, SM_TOT>>>(out);
}

// round 8
// speedup vs baseline: 1.0611x; 1.0611x over previous
#include <cuda_runtime.h>
#include <cstdint>

#define NN 3072
#define DD 128
#define HID 256
#define NAA 20
#define NH 8
#define TM 16          // rows per prep block
#define JT 64          // j-tile per pair CTA
#define IT 16          // i-rows per pair CTA
#define TI 4           // i-rows per pair thread

typedef unsigned long long ull;

// Scratch (allocation-free rule: __device__ globals)
// dgate, block-transposed: float index = jb*10240 + (xp*4 + b/2)*256 + jj*4 + (b&1)*2 + (x&1)
__device__ __align__(16) float g_dgT[48 * 40 * 256];
// ctilde: row layout [xp*16 + b*2 + e], 160 floats per row
__device__ __align__(16) float g_ctilde[NN * 160];

// gelu(v) = 0.5 v (1 + tanh(u)) = v * sigmoid(2u),  u = sqrt(2/pi)(v + 0.044715 v^3)
__device__ __forceinline__ float gelu_tanh(float v) {
    float u = 0.7978845608028654f * (v + 0.044715f * v * v * v);
    float e = __expf(-2.0f * u);
    return v / (1.0f + e);
}

__device__ __forceinline__ ull fma2(ull a, ull b, ull c) {
    ull d;
    asm("fma.rn.f32x2 %0, %1, %2, %3;" : "=l"(d) : "l"(a), "l"(b), "l"(c));
    return d;
}

__device__ __forceinline__ uint32_t smem_u32(const void* p) {
    uint32_t a;
    asm("{ .reg .u64 t; cvta.to.shared.u64 t, %1; cvt.u32.u64 %0, t; }" : "=r"(a) : "l"(p));
    return a;
}

// ============================================================================
// Kernel A: fused MLP + projections + ctilde / dgate precompute (TM=16, 256T)
// ============================================================================
__global__ __launch_bounds__(256) void prep_kernel(
    const float* __restrict__ local, const int* __restrict__ aa,
    const float* __restrict__ W1, const float* __restrict__ W2,
    const float* __restrict__ Wc, const float* __restrict__ Wg,
    const float* __restrict__ iw)
{
    __shared__ __align__(16) float xs[TM][DD];
    __shared__ __align__(16) float Hs[TM][HID];
    __shared__ __align__(16) float Fs[TM][DD];
    __shared__ __align__(16) float dcs[TM][160];
    __shared__ __align__(16) float dgs[40 * 64];
    __shared__ float iws[NH * NH * NAA];
    __shared__ int aas[TM];

    const int tid = threadIdx.x;
    const int r0 = blockIdx.x * TM;

    for (int t = tid; t < TM * DD; t += 256) {
        int r = t / DD, k = t % DD;
        xs[r][k] = local[(size_t)(r0 + r) * DD + k];
    }
    for (int t = tid; t < NH * NH * NAA; t += 256) iws[t] = iw[t];
    if (tid < TM) aas[tid] = aa[r0 + tid];
    __syncthreads();

    // ---- stage 1: H = gelu(local @ W1[:128] + W1[128+aa]) ----
    {
        float acc[TM];
#pragma unroll
        for (int r = 0; r < TM; r++) acc[r] = 0.f;
        const int col = tid;
#pragma unroll 8
        for (int k = 0; k < DD; k += 4) {
            float w0 = W1[(size_t)(k + 0) * HID + col];
            float w1 = W1[(size_t)(k + 1) * HID + col];
            float w2 = W1[(size_t)(k + 2) * HID + col];
            float w3 = W1[(size_t)(k + 3) * HID + col];
#pragma unroll
            for (int r = 0; r < TM; r++) {
                float4 xv = *(const float4*)&xs[r][k];
                acc[r] = fmaf(xv.x, w0, fmaf(xv.y, w1, fmaf(xv.z, w2, fmaf(xv.w, w3, acc[r]))));
            }
        }
#pragma unroll
        for (int r = 0; r < TM; r++) {
            acc[r] += W1[(size_t)(DD + aas[r]) * HID + col];
            Hs[r][col] = gelu_tanh(acc[r]);
        }
    }
    __syncthreads();

    // ---- stage 2: F = H @ W2 ----
    {
        float acc[8];
#pragma unroll
        for (int r = 0; r < 8; r++) acc[r] = 0.f;
        const int col = tid & 127;
        const int rb = (tid >> 7) * 8;
#pragma unroll 8
        for (int k = 0; k < HID; k += 4) {
            float w0 = W2[(size_t)(k + 0) * DD + col];
            float w1 = W2[(size_t)(k + 1) * DD + col];
            float w2 = W2[(size_t)(k + 2) * DD + col];
            float w3 = W2[(size_t)(k + 3) * DD + col];
#pragma unroll
            for (int r = 0; r < 8; r++) {
                float4 hv = *(const float4*)&Hs[rb + r][k];
                acc[r] = fmaf(hv.x, w0, fmaf(hv.y, w1, fmaf(hv.z, w2, fmaf(hv.w, w3, acc[r]))));
            }
        }
#pragma unroll
        for (int r = 0; r < 8; r++) Fs[rb + r][col] = acc[r];
    }
    __syncthreads();

    // ---- stage 3: dcode = F@Wc (smem), dgate = gelu(F@Wg) -> smem dgs ----
    for (int c = tid; c < 320; c += 256) {
        float acc[TM];
#pragma unroll
        for (int r = 0; r < TM; r++) acc[r] = 0.f;
        const float* W = (c < 160) ? (Wc + c) : (Wg + (c - 160));
#pragma unroll 8
        for (int k = 0; k < DD; k += 4) {
            float w0 = W[(size_t)(k + 0) * 160];
            float w1 = W[(size_t)(k + 1) * 160];
            float w2 = W[(size_t)(k + 2) * 160];
            float w3 = W[(size_t)(k + 3) * 160];
#pragma unroll
            for (int r = 0; r < TM; r++) {
                float4 fv = *(const float4*)&Fs[r][k];
                acc[r] = fmaf(fv.x, w0, fmaf(fv.y, w1, fmaf(fv.z, w2, fmaf(fv.w, w3, acc[r]))));
            }
        }
        if (c < 160) {
#pragma unroll
            for (int r = 0; r < TM; r++) dcs[r][c] = acc[r];
        } else {
            int cc = c - 160;
            int b = cc / NAA, x = cc % NAA;
            int row = (x >> 1) * 4 + (b >> 1);
            int e   = (b & 1) * 2 + (x & 1);
#pragma unroll
            for (int r = 0; r < TM; r++)
                dgs[row * 64 + r * 4 + e] = gelu_tanh(acc[r]);
        }
    }
    __syncthreads();

    // ---- coalesced copy: dgs -> g_dgT ----
    {
        const int jb = r0 >> 6;
        const int jo = (r0 & 63) >> 2;
        const float4* src = (const float4*)dgs;
        float4* dst = (float4*)g_dgT;
        for (int t = tid; t < 640; t += 256) {
            int row = t >> 4, q = t & 15;
            dst[(size_t)jb * 2560 + row * 64 + jo * 4 + q] = src[row * 16 + q];
        }
    }

    // ---- stage 4: ctilde[r,b,x] = sum_a dcode[r,a,x] * iw[a,b,x] ----
    for (int t = tid; t < TM * 160; t += 256) {
        int r = t / 160, rem = t % 160;
        int b = rem / NAA, x = rem % NAA;
        float s = 0.f;
#pragma unroll
        for (int a = 0; a < NH; a++)
            s = fmaf(dcs[r][a * NAA + x], iws[a * 160 + b * NAA + x], s);
        g_ctilde[(size_t)(r0 + r) * 160 + (x >> 1) * 16 + b * 2 + (x & 1)] = s;
    }
}

// ============================================================================
// Kernel B: pairwise bilinear + log_softmax (exact R6 revert — proven 176 us)
// ============================================================================
#define SM_GS   0
#define SM_CS   40960
#define SM_STG  51200
#define SM_MBAR 92160
#define SM_TOT  92176

__global__ __launch_bounds__(256, 2) void pair_kernel(float* __restrict__ out)
{
    extern __shared__ __align__(16) char sm[];
    const ulonglong2* gs2 = (const ulonglong2*)(sm + SM_GS);  // [40][64]
    const float*      cs  = (const float*)(sm + SM_CS);       // [16][160]

    const uint32_t sb   = smem_u32(sm);
    const uint32_t mbar = sb + SM_MBAR;

    const int tid  = threadIdx.x;
    const int lane = tid & 31;
    const int wid  = tid >> 5;
    const int i0   = blockIdx.x * IT;
    const int jb   = blockIdx.y;

    if (tid == 0) {
        asm volatile("mbarrier.init.shared::cta.b64 [%0], %1;" :: "r"(mbar), "r"(1) : "memory");
    }
    __syncthreads();
    if (tid == 0) {
        asm volatile("mbarrier.arrive.expect_tx.shared::cta.b64 _, [%0], %1;"
                     :: "r"(mbar), "r"(51200) : "memory");
        asm volatile("cp.async.bulk.shared::cta.global.mbarrier::complete_tx::bytes [%0], [%1], %2, [%3];"
                     :: "r"(sb + SM_GS), "l"(g_dgT + (size_t)jb * 10240), "r"(40960), "r"(mbar) : "memory");
        asm volatile("cp.async.bulk.shared::cta.global.mbarrier::complete_tx::bytes [%0], [%1], %2, [%3];"
                     :: "r"(sb + SM_CS), "l"(g_ctilde + (size_t)i0 * 160), "r"(10240), "r"(mbar) : "memory");
    }
    asm volatile("{\n\t.reg .pred P;\n"
                 "W%=: mbarrier.try_wait.parity.shared::cta.b64 P, [%0], 0;\n\t"
                 "@!P bra W%=;\n\t}" :: "r"(mbar) : "memory");
    __syncthreads();

    const int jj = tid & 63;
    const int ig = tid >> 6;

    ull acc[TI][10];
#pragma unroll
    for (int r = 0; r < TI; r++)
#pragma unroll
        for (int q = 0; q < 10; q++) acc[r][q] = 0ULL;

#pragma unroll
    for (int xp = 0; xp < 10; xp++) {
        ulonglong2 g0  = gs2[(xp * 4 + 0) * 64 + jj];
        ulonglong2 g1  = gs2[(xp * 4 + 1) * 64 + jj];
        ulonglong2 g2v = gs2[(xp * 4 + 2) * 64 + jj];
        ulonglong2 g3  = gs2[(xp * 4 + 3) * 64 + jj];
#pragma unroll
        for (int r = 0; r < TI; r++) {
            const float* cp = cs + (ig * 4 + r) * 160 + xp * 16;
            longlong2 ca = *(const longlong2*)(cp);
            longlong2 cb = *(const longlong2*)(cp + 4);
            longlong2 cc = *(const longlong2*)(cp + 8);
            longlong2 cd = *(const longlong2*)(cp + 12);
            ull a0 = acc[r][xp];
            a0 = fma2((ull)ca.x, g0.x, a0);
            a0 = fma2((ull)ca.y, g0.y, a0);
            a0 = fma2((ull)cb.x, g1.x, a0);
            a0 = fma2((ull)cb.y, g1.y, a0);
            a0 = fma2((ull)cc.x, g2v.x, a0);
            a0 = fma2((ull)cc.y, g2v.y, a0);
            a0 = fma2((ull)cd.x, g3.x, a0);
            a0 = fma2((ull)cd.y, g3.y, a0);
            acc[r][xp] = a0;
        }
    }

    // ---- epilogue: log_softmax, stage (conflict-free STS.128), bulk store ----
    float* wbuf = (float*)(sm + SM_STG) + wid * 1280;
    const uint32_t wbuf_u32 = sb + SM_STG + wid * 5120;
    const int col0 = jb * JT + (wid & 1) * 32;

#pragma unroll
    for (int r = 0; r < TI; r++) {
        float* st = wbuf + (r & 1) * 640;
        if (r >= 2 && lane == 0)
            asm volatile("cp.async.bulk.wait_group.read 1;" ::: "memory");
        __syncwarp();

        float l[20];
#pragma unroll
        for (int q = 0; q < 10; q++) {
            l[2 * q]     = __uint_as_float((unsigned)(acc[r][q] & 0xffffffffu));
            l[2 * q + 1] = __uint_as_float((unsigned)(acc[r][q] >> 32));
        }
        float m = l[0];
#pragma unroll
        for (int x = 1; x < 20; x++) m = fmaxf(m, l[x]);
        float s = 0.f;
#pragma unroll
        for (int x = 0; x < 20; x++) s += __expf(l[x] - m);
        float lse = m + __logf(s);

        float* tp = st + lane * 20;
#pragma unroll
        for (int q = 0; q < 5; q++) {
            float4 o = make_float4(l[4 * q] - lse, l[4 * q + 1] - lse,
                                   l[4 * q + 2] - lse, l[4 * q + 3] - lse);
            *(float4*)(tp + 4 * q) = o;
        }
        __syncwarp();

        if (lane == 0) {
            float* gdst = out + ((size_t)(i0 + ig * 4 + r) * NN + col0) * NAA;
            asm volatile("fence.proxy.async.shared::cta;" ::: "memory");
            asm volatile("cp.async.bulk.global.shared::cta.bulk_group [%0], [%1], %2;"
                         :: "l"(gdst), "r"(wbuf_u32 + (r & 1) * 2560), "r"(2560) : "memory");
            asm volatile("cp.async.bulk.commit_group;" ::: "memory");
        }
    }
    if (lane == 0)
        asm volatile("cp.async.bulk.wait_group 0;" ::: "memory");
}

// ============================================================================
extern "C" void kernel_launch(void* const* d_in, const int* in_sizes, int n_in,
                              void* d_out, int out_size)
{
    const float* local = (const float*)d_in[0];
    const int*   aa    = (const int*)d_in[1];
    const float* W1    = (const float*)d_in[2];
    const float* W2    = (const float*)d_in[3];
    const float* Wc    = (const float*)d_in[4];
    const float* Wg    = (const float*)d_in[5];
    const float* iw    = (const float*)d_in[6];
    float* out = (float*)d_out;

    prep_kernel<<<NN / TM, 256>>>(local, aa, W1, W2, Wc, Wg, iw);

    cudaFuncSetAttribute(pair_kernel, cudaFuncAttributeMaxDynamicSharedMemorySize, SM_TOT);
    dim3 grid(NN / IT, NN / JT);
    pair_kernel<<<grid, 256, SM_TOT>>>(out);
}